// round 11
// baseline (speedup 1.0000x reference)
#include <cuda_runtime.h>
#include <cuda_fp16.h>

#define NN     100000
#define DIN    128
#define DHID   64
#define DOUT   6
#define MAXDEG 64
#define NEG    0.2f

// ---------------- static device scratch ----------------
__device__ __half2 g_h1h[(size_t)NN * 32];     // h1 fp16, [node][32] half2
__device__ float g_h2[(size_t)NN * DOUT];
__device__ float g_s1[NN], g_d1[NN];
__device__ float g_s2[NN], g_d2[NN];
__device__ int   g_cnt[NN];                    // per-node degree counter (memset to 0)
__device__ int2  g_csr2d[(size_t)NN * MAXDEG]; // per-edge {src, f32bits(s1[src])}
__device__ int   g_is64;

// ---------------- tf32 helpers ----------------
__device__ __forceinline__ unsigned f2tf32(float f) {
    unsigned r;
    asm("cvt.rna.tf32.f32 %0, %1;" : "=r"(r) : "f"(f));
    return r;
}

__device__ __forceinline__ void mma_tf32(float* c, const unsigned* a, const unsigned* b) {
    asm volatile(
        "mma.sync.aligned.m16n8k8.row.col.f32.tf32.tf32.f32 "
        "{%0,%1,%2,%3}, {%4,%5,%6,%7}, {%8,%9}, {%0,%1,%2,%3};"
        : "+f"(c[0]), "+f"(c[1]), "+f"(c[2]), "+f"(c[3])
        : "r"(a[0]), "r"(a[1]), "r"(a[2]), "r"(a[3]), "r"(b[0]), "r"(b[1]));
}

// ---------------- dtype detection (1 block) ----------------
__global__ void k_detect(const int* __restrict__ w, int n_words) {
    __shared__ int nz;
    if (threadIdx.x == 0) nz = 0;
    __syncthreads();
    for (int k = threadIdx.x; k < 2048; k += blockDim.x) {
        int idx = 2 * k + 1;
        if (idx < n_words && w[idx] != 0) atomicAdd(&nz, 1);
    }
    __syncthreads();
    if (threadIdx.x == 0) g_is64 = (nz == 0) ? 1 : 0;
}

__device__ __forceinline__ int read_ei(const void* p, long long i) {
    if (g_is64) return (int)((const long long*)p)[i];
    return ((const int*)p)[i];
}

// ---------------- GEMM1 (tf32 tensor cores) -> h1 (fp16) + fused s1/d1 ----------------
__global__ void k_gemm1_tc(const float* __restrict__ x, const float* __restrict__ W,
                           const float* __restrict__ as, const float* __restrict__ ad) {
    __shared__ unsigned ws[DIN][72];
    int t    = threadIdx.x;
    int lane = t & 31;
    int warp = t >> 5;
    int m0   = blockIdx.x * 128;

    for (int i = t; i < DIN * DHID; i += 256) {
        int k = i >> 6, n = i & 63;
        ws[k][n] = f2tf32(W[k * DHID + n]);
    }
    __syncthreads();

    int r0 = m0 + warp * 16 + (lane >> 2);
    bool v0 = r0 < NN, v1 = (r0 + 8) < NN;
    const float* xp0 = x + (size_t)r0 * DIN + (lane & 3);
    const float* xp1 = xp0 + (size_t)8 * DIN;

    float c[8][4];
#pragma unroll
    for (int nc = 0; nc < 8; ++nc)
#pragma unroll
        for (int j = 0; j < 4; ++j) c[nc][j] = 0.f;

#pragma unroll
    for (int kc = 0; kc < 16; ++kc) {
        int ko = kc * 8;
        unsigned a[4];
        a[0] = v0 ? f2tf32(__ldg(&xp0[ko]))     : 0u;
        a[1] = v1 ? f2tf32(__ldg(&xp1[ko]))     : 0u;
        a[2] = v0 ? f2tf32(__ldg(&xp0[ko + 4])) : 0u;
        a[3] = v1 ? f2tf32(__ldg(&xp1[ko + 4])) : 0u;
#pragma unroll
        for (int nc = 0; nc < 8; ++nc) {
            unsigned b[2];
            b[0] = ws[ko + (lane & 3)][nc * 8 + (lane >> 2)];
            b[1] = ws[ko + (lane & 3) + 4][nc * 8 + (lane >> 2)];
            mma_tf32(c[nc], a, b);
        }
    }

    float slo = 0.f, shi = 0.f, dlo = 0.f, dhi = 0.f;
#pragma unroll
    for (int nc = 0; nc < 8; ++nc) {
        int col = nc * 8 + 2 * (lane & 3);
        float as0 = as[col], as1 = as[col + 1];
        float ad0 = ad[col], ad1 = ad[col + 1];
        slo += c[nc][0] * as0 + c[nc][1] * as1;
        dlo += c[nc][0] * ad0 + c[nc][1] * ad1;
        shi += c[nc][2] * as0 + c[nc][3] * as1;
        dhi += c[nc][2] * ad0 + c[nc][3] * ad1;
        int h2i = nc * 4 + (lane & 3);
        if (v0) g_h1h[(size_t)r0 * 32 + h2i]       = __float22half2_rn(make_float2(c[nc][0], c[nc][1]));
        if (v1) g_h1h[(size_t)(r0 + 8) * 32 + h2i] = __float22half2_rn(make_float2(c[nc][2], c[nc][3]));
    }
    slo += __shfl_xor_sync(0xffffffffu, slo, 1); slo += __shfl_xor_sync(0xffffffffu, slo, 2);
    dlo += __shfl_xor_sync(0xffffffffu, dlo, 1); dlo += __shfl_xor_sync(0xffffffffu, dlo, 2);
    shi += __shfl_xor_sync(0xffffffffu, shi, 1); shi += __shfl_xor_sync(0xffffffffu, shi, 2);
    dhi += __shfl_xor_sync(0xffffffffu, dhi, 1); dhi += __shfl_xor_sync(0xffffffffu, dhi, 2);
    if ((lane & 3) == 0) {
        if (v0) { g_s1[r0] = slo;     g_d1[r0] = dlo; }
        if (v1) { g_s1[r0 + 8] = shi; g_d1[r0 + 8] = dhi; }
    }
}

// ---------------- CSR fill AFTER gemm1: store {src, f32bits(s1[src])} ----------------
__global__ void k_fill2d(const void* __restrict__ ei, int E, int EP) {
    int i = blockIdx.x * blockDim.x + threadIdx.x;
    if (i >= EP) return;
    int s, d;
    if (i < E) {
        s = read_ei(ei, i);
        d = read_ei(ei, (long long)E + i);
    } else {
        s = d = i - E;  // self loop
    }
    if (d < 0 || d >= NN || s < 0 || s >= NN) return;
    float sv = g_s1[s];
    int pos = atomicAdd(&g_cnt[d], 1);
    if (pos < MAXDEG) g_csr2d[(size_t)d * MAXDEG + pos] = make_int2(s, __float_as_int(sv));
}

// ---------------- layer-1 GAT (online softmax, coalesced pair load) + fused layer-2 linear ----------------
__global__ void k_edge64(const float* __restrict__ bias, const float* __restrict__ W2,
                         const float* __restrict__ as2, const float* __restrict__ ad2) {
    int w    = (blockIdx.x * blockDim.x + threadIdx.x) >> 5;
    int lane = threadIdx.x & 31;
    if (w >= NN) return;
    int deg = min(g_cnt[w], MAXDEG);
    const int2* csr = g_csr2d + (size_t)w * MAXDEG;
    float dv = g_d1[w];

    float m_run = -1e30f, den = 0.f, acc0 = 0.f, acc1 = 0.f;
    for (int base = 0; base < deg; base += 32) {
        int j = base + lane;
        float e = -1e30f;
        int si = 0;
        if (j < deg) {
            int2 pr = csr[j];           // coalesced 8B/lane
            si = pr.x;
            e = __int_as_float(pr.y) + dv;
            e = (e > 0.f) ? e : NEG * e;
        }
        float sm = e;
#pragma unroll
        for (int o = 16; o; o >>= 1) sm = fmaxf(sm, __shfl_xor_sync(0xffffffffu, sm, o));
        float newm  = fmaxf(m_run, sm);
        float scale = __expf(m_run - newm);
        den *= scale; acc0 *= scale; acc1 *= scale;
        m_run = newm;
        float ex = __expf(e - newm);    // inactive lanes -> 0
        den += ex;

        int cnt = min(32, deg - base);
        int t = 0;
        for (; t + 4 <= cnt; t += 4) {
            float e0 = __shfl_sync(0xffffffffu, ex, t + 0);
            float e1 = __shfl_sync(0xffffffffu, ex, t + 1);
            float e2 = __shfl_sync(0xffffffffu, ex, t + 2);
            float e3 = __shfl_sync(0xffffffffu, ex, t + 3);
            int   s0 = __shfl_sync(0xffffffffu, si, t + 0);
            int   s1 = __shfl_sync(0xffffffffu, si, t + 1);
            int   s2 = __shfl_sync(0xffffffffu, si, t + 2);
            int   s3 = __shfl_sync(0xffffffffu, si, t + 3);
            float2 f0 = __half22float2(g_h1h[(size_t)s0 * 32 + lane]);
            float2 f1 = __half22float2(g_h1h[(size_t)s1 * 32 + lane]);
            float2 f2 = __half22float2(g_h1h[(size_t)s2 * 32 + lane]);
            float2 f3 = __half22float2(g_h1h[(size_t)s3 * 32 + lane]);
            acc0 = fmaf(e0, f0.x, acc0); acc1 = fmaf(e0, f0.y, acc1);
            acc0 = fmaf(e1, f1.x, acc0); acc1 = fmaf(e1, f1.y, acc1);
            acc0 = fmaf(e2, f2.x, acc0); acc1 = fmaf(e2, f2.y, acc1);
            acc0 = fmaf(e3, f3.x, acc0); acc1 = fmaf(e3, f3.y, acc1);
        }
        for (; t < cnt; ++t) {
            float ej = __shfl_sync(0xffffffffu, ex, t);
            int   sj = __shfl_sync(0xffffffffu, si, t);
            float2 f = __half22float2(g_h1h[(size_t)sj * 32 + lane]);
            acc0 = fmaf(ej, f.x, acc0);
            acc1 = fmaf(ej, f.y, acc1);
        }
    }
#pragma unroll
    for (int o = 16; o; o >>= 1) den += __shfl_xor_sync(0xffffffffu, den, o);

    float inv = 1.f / den;
    float2 bv = ((const float2*)bias)[lane];
    float o0 = acc0 * inv + bv.x;
    float o1 = acc1 * inv + bv.y;
    o0 = (o0 > 0.f) ? o0 : expm1f(o0);  // ELU
    o1 = (o1 > 0.f) ? o1 : expm1f(o1);

    // fused layer-2 linear: h2/s2/d2
    float p[DOUT];
#pragma unroll
    for (int c = 0; c < DOUT; ++c)
        p[c] = o0 * W2[(2 * lane) * DOUT + c] + o1 * W2[(2 * lane + 1) * DOUT + c];
#pragma unroll
    for (int c = 0; c < DOUT; ++c)
#pragma unroll
        for (int o = 16; o; o >>= 1) p[c] += __shfl_xor_sync(0xffffffffu, p[c], o);
    if (lane == 0) {
        float s = 0.f, d = 0.f;
#pragma unroll
        for (int c = 0; c < DOUT; ++c) {
            g_h2[(size_t)w * DOUT + c] = p[c];
            s += p[c] * as2[c];
            d += p[c] * ad2[c];
        }
        g_s2[w] = s;
        g_d2[w] = d;
    }
}

// ---------------- layer-2 GAT (C=6, online softmax) ----------------
__global__ void k_edge6(const float* __restrict__ b2, float* __restrict__ out) {
    int w    = (blockIdx.x * blockDim.x + threadIdx.x) >> 5;
    int lane = threadIdx.x & 31;
    if (w >= NN) return;
    int deg = min(g_cnt[w], MAXDEG);
    const int2* csr = g_csr2d + (size_t)w * MAXDEG;
    float dv = g_d2[w];

    float m_run = -1e30f, den = 0.f;
    float a0 = 0.f, a1 = 0.f, a2 = 0.f, a3 = 0.f, a4 = 0.f, a5 = 0.f;
    for (int base = 0; base < deg; base += 32) {
        int j = base + lane;
        float e = -1e30f;
        int si = 0;
        if (j < deg) {
            si = csr[j].x;
            e = g_s2[si] + dv;
            e = (e > 0.f) ? e : NEG * e;
        }
        float sm = e;
#pragma unroll
        for (int o = 16; o; o >>= 1) sm = fmaxf(sm, __shfl_xor_sync(0xffffffffu, sm, o));
        float newm  = fmaxf(m_run, sm);
        float scale = __expf(m_run - newm);
        den *= scale; a0 *= scale; a1 *= scale; a2 *= scale;
        a3 *= scale; a4 *= scale; a5 *= scale;
        m_run = newm;
        float ex = (j < deg) ? __expf(e - newm) : 0.f;
        den += ex;
        if (j < deg) {
            const float2* hp = (const float2*)g_h2 + (size_t)si * 3;
            float2 v0 = hp[0], v1 = hp[1], v2 = hp[2];
            a0 = fmaf(ex, v0.x, a0); a1 = fmaf(ex, v0.y, a1);
            a2 = fmaf(ex, v1.x, a2); a3 = fmaf(ex, v1.y, a3);
            a4 = fmaf(ex, v2.x, a4); a5 = fmaf(ex, v2.y, a5);
        }
    }
#pragma unroll
    for (int o = 16; o; o >>= 1) {
        den += __shfl_xor_sync(0xffffffffu, den, o);
        a0 += __shfl_xor_sync(0xffffffffu, a0, o);
        a1 += __shfl_xor_sync(0xffffffffu, a1, o);
        a2 += __shfl_xor_sync(0xffffffffu, a2, o);
        a3 += __shfl_xor_sync(0xffffffffu, a3, o);
        a4 += __shfl_xor_sync(0xffffffffu, a4, o);
        a5 += __shfl_xor_sync(0xffffffffu, a5, o);
    }
    if (lane == 0) {
        float inv = 1.f / den;
        out[(size_t)w * DOUT + 0] = a0 * inv + b2[0];
        out[(size_t)w * DOUT + 1] = a1 * inv + b2[1];
        out[(size_t)w * DOUT + 2] = a2 * inv + b2[2];
        out[(size_t)w * DOUT + 3] = a3 * inv + b2[3];
        out[(size_t)w * DOUT + 4] = a4 * inv + b2[4];
        out[(size_t)w * DOUT + 5] = a5 * inv + b2[5];
    }
}

// ---------------- launch ----------------
extern "C" void kernel_launch(void* const* d_in, const int* in_sizes, int n_in,
                              void* d_out, int out_size) {
    const float* x      = (const float*)d_in[0];
    const void*  ei     = d_in[1];
    const float* W1     = (const float*)d_in[2];
    const float* a_src1 = (const float*)d_in[3];
    const float* a_dst1 = (const float*)d_in[4];
    const float* b1     = (const float*)d_in[5];
    const float* W2     = (const float*)d_in[6];
    const float* a_src2 = (const float*)d_in[7];
    const float* a_dst2 = (const float*)d_in[8];
    const float* b2     = (const float*)d_in[9];
    float*       out    = (float*)d_out;

    int E  = in_sizes[1] / 2;
    int EP = E + NN;
    int n_words = in_sizes[1];

    // zero degree counters (graph-capturable async memset)
    void* cnt_ptr = nullptr;
    cudaGetSymbolAddress(&cnt_ptr, g_cnt);
    cudaMemsetAsync(cnt_ptr, 0, NN * sizeof(int));

    // dtype detect (tiny)
    k_detect<<<1, 256>>>((const int*)ei, n_words);

    // layer-1 GEMM (tensor cores) + fused s1/d1  — BEFORE fill so fill can pack s1
    k_gemm1_tc<<<(NN + 127) / 128, 256>>>(x, W1, a_src1, a_dst1);

    // CSR fill: {src, s1[src]} pairs
    k_fill2d<<<(EP + 255) / 256, 256>>>(ei, E, EP);

    // layer-1 GAT (online softmax) + fused layer-2 linear
    int warp_blocks = (NN * 32 + 255) / 256;
    k_edge64<<<warp_blocks, 256>>>(b1, W2, a_src2, a_dst2);

    // layer-2 GAT
    k_edge6<<<warp_blocks, 256>>>(b2, out);
}

// round 12
// speedup vs baseline: 1.0723x; 1.0723x over previous
#include <cuda_runtime.h>
#include <cuda_fp16.h>

#define NN     100000
#define DIN    128
#define DHID   64
#define DOUT   6
#define MAXDEG 64
#define NEG    0.2f

// ---------------- static device scratch ----------------
__device__ __half2 g_h1h[(size_t)NN * 32];     // h1 fp16, [node][32] half2
__device__ float g_h2[(size_t)NN * DOUT];
__device__ float g_s1[NN], g_d1[NN];
__device__ float g_s2[NN], g_d2[NN];
__device__ int   g_cnt[NN];                    // per-node degree counter (memset to 0)
__device__ int2  g_csr2d[(size_t)NN * MAXDEG]; // per-edge {src*32, f32bits(s1[src])}
__device__ int   g_is64;

// ---------------- tf32 helpers ----------------
__device__ __forceinline__ unsigned f2tf32(float f) {
    unsigned r;
    asm("cvt.rna.tf32.f32 %0, %1;" : "=r"(r) : "f"(f));
    return r;
}

__device__ __forceinline__ void mma_tf32(float* c, const unsigned* a, const unsigned* b) {
    asm volatile(
        "mma.sync.aligned.m16n8k8.row.col.f32.tf32.tf32.f32 "
        "{%0,%1,%2,%3}, {%4,%5,%6,%7}, {%8,%9}, {%0,%1,%2,%3};"
        : "+f"(c[0]), "+f"(c[1]), "+f"(c[2]), "+f"(c[3])
        : "r"(a[0]), "r"(a[1]), "r"(a[2]), "r"(a[3]), "r"(b[0]), "r"(b[1]));
}

// ---------------- dtype detection (1 block) ----------------
__global__ void k_detect(const int* __restrict__ w, int n_words) {
    __shared__ int nz;
    if (threadIdx.x == 0) nz = 0;
    __syncthreads();
    for (int k = threadIdx.x; k < 2048; k += blockDim.x) {
        int idx = 2 * k + 1;
        if (idx < n_words && w[idx] != 0) atomicAdd(&nz, 1);
    }
    __syncthreads();
    if (threadIdx.x == 0) g_is64 = (nz == 0) ? 1 : 0;
}

__device__ __forceinline__ int read_ei(const void* p, long long i) {
    if (g_is64) return (int)((const long long*)p)[i];
    return ((const int*)p)[i];
}

// ---------------- GEMM1 (tf32 tensor cores) -> h1 (fp16) + fused s1/d1 ----------------
__global__ void k_gemm1_tc(const float* __restrict__ x, const float* __restrict__ W,
                           const float* __restrict__ as, const float* __restrict__ ad) {
    __shared__ unsigned ws[DIN][72];
    int t    = threadIdx.x;
    int lane = t & 31;
    int warp = t >> 5;
    int m0   = blockIdx.x * 128;

    for (int i = t; i < DIN * DHID; i += 256) {
        int k = i >> 6, n = i & 63;
        ws[k][n] = f2tf32(W[k * DHID + n]);
    }
    __syncthreads();

    int r0 = m0 + warp * 16 + (lane >> 2);
    bool v0 = r0 < NN, v1 = (r0 + 8) < NN;
    const float* xp0 = x + (size_t)r0 * DIN + (lane & 3);
    const float* xp1 = xp0 + (size_t)8 * DIN;

    float c[8][4];
#pragma unroll
    for (int nc = 0; nc < 8; ++nc)
#pragma unroll
        for (int j = 0; j < 4; ++j) c[nc][j] = 0.f;

#pragma unroll
    for (int kc = 0; kc < 16; ++kc) {
        int ko = kc * 8;
        unsigned a[4];
        a[0] = v0 ? f2tf32(__ldg(&xp0[ko]))     : 0u;
        a[1] = v1 ? f2tf32(__ldg(&xp1[ko]))     : 0u;
        a[2] = v0 ? f2tf32(__ldg(&xp0[ko + 4])) : 0u;
        a[3] = v1 ? f2tf32(__ldg(&xp1[ko + 4])) : 0u;
#pragma unroll
        for (int nc = 0; nc < 8; ++nc) {
            unsigned b[2];
            b[0] = ws[ko + (lane & 3)][nc * 8 + (lane >> 2)];
            b[1] = ws[ko + (lane & 3) + 4][nc * 8 + (lane >> 2)];
            mma_tf32(c[nc], a, b);
        }
    }

    float slo = 0.f, shi = 0.f, dlo = 0.f, dhi = 0.f;
#pragma unroll
    for (int nc = 0; nc < 8; ++nc) {
        int col = nc * 8 + 2 * (lane & 3);
        float as0 = as[col], as1 = as[col + 1];
        float ad0 = ad[col], ad1 = ad[col + 1];
        slo += c[nc][0] * as0 + c[nc][1] * as1;
        dlo += c[nc][0] * ad0 + c[nc][1] * ad1;
        shi += c[nc][2] * as0 + c[nc][3] * as1;
        dhi += c[nc][2] * ad0 + c[nc][3] * ad1;
        int h2i = nc * 4 + (lane & 3);
        if (v0) g_h1h[(size_t)r0 * 32 + h2i]       = __float22half2_rn(make_float2(c[nc][0], c[nc][1]));
        if (v1) g_h1h[(size_t)(r0 + 8) * 32 + h2i] = __float22half2_rn(make_float2(c[nc][2], c[nc][3]));
    }
    slo += __shfl_xor_sync(0xffffffffu, slo, 1); slo += __shfl_xor_sync(0xffffffffu, slo, 2);
    dlo += __shfl_xor_sync(0xffffffffu, dlo, 1); dlo += __shfl_xor_sync(0xffffffffu, dlo, 2);
    shi += __shfl_xor_sync(0xffffffffu, shi, 1); shi += __shfl_xor_sync(0xffffffffu, shi, 2);
    dhi += __shfl_xor_sync(0xffffffffu, dhi, 1); dhi += __shfl_xor_sync(0xffffffffu, dhi, 2);
    if ((lane & 3) == 0) {
        if (v0) { g_s1[r0] = slo;     g_d1[r0] = dlo; }
        if (v1) { g_s1[r0 + 8] = shi; g_d1[r0 + 8] = dhi; }
    }
}

// ---------------- CSR fill AFTER gemm1: store {src*32, f32bits(s1[src])} ----------------
__global__ void k_fill2d(const void* __restrict__ ei, int E, int EP) {
    int i = blockIdx.x * blockDim.x + threadIdx.x;
    if (i >= EP) return;
    int s, d;
    if (i < E) {
        s = read_ei(ei, i);
        d = read_ei(ei, (long long)E + i);
    } else {
        s = d = i - E;  // self loop
    }
    if (d < 0 || d >= NN || s < 0 || s >= NN) return;
    float sv = g_s1[s];
    int pos = atomicAdd(&g_cnt[d], 1);
    if (pos < MAXDEG) g_csr2d[(size_t)d * MAXDEG + pos] = make_int2(s << 5, __float_as_int(sv));
}

// ---------------- layer-1 GAT (online softmax, smem weight stage) + fused layer-2 linear ----------------
__global__ void k_edge64(const float* __restrict__ bias, const float* __restrict__ W2,
                         const float* __restrict__ as2, const float* __restrict__ ad2) {
    __shared__ int2 sw[8][32];
    int tid  = threadIdx.x;
    int wip  = tid >> 5;
    int lane = tid & 31;
    int w    = (blockIdx.x * blockDim.x + tid) >> 5;
    if (w >= NN) return;
    int deg = min(g_cnt[w], MAXDEG);
    const int2* csr = g_csr2d + (size_t)w * MAXDEG;
    float dv = g_d1[w];
    const __half2* hbase = g_h1h + lane;   // hbase[s*32] = g_h1h[s*32 + lane]

    float m_run = -1e30f, den = 0.f, acc0 = 0.f, acc1 = 0.f;
    for (int base = 0; base < deg; base += 32) {
        int j = base + lane;
        float e = -1e30f;
        int si32 = 0;
        if (j < deg) {
            int2 pr = csr[j];               // coalesced 8B/lane
            si32 = pr.x;                    // src*32
            float ee = __int_as_float(pr.y) + dv;
            e = (ee > 0.f) ? ee : NEG * ee;
        }
        float sm = e;
#pragma unroll
        for (int o = 16; o; o >>= 1) sm = fmaxf(sm, __shfl_xor_sync(0xffffffffu, sm, o));
        float newm  = fmaxf(m_run, sm);
        float scale = __expf(m_run - newm);
        den *= scale; acc0 *= scale; acc1 *= scale;
        m_run = newm;
        float ex = __expf(e - newm);        // inactive lanes -> 0
        den += ex;
        sw[wip][lane] = make_int2(si32, __float_as_int(ex));
        __syncwarp();

        int cnt = min(32, deg - base);
        int t = 0;
        for (; t + 4 <= cnt; t += 4) {
            int2 p0 = sw[wip][t + 0];
            int2 p1 = sw[wip][t + 1];
            int2 p2 = sw[wip][t + 2];
            int2 p3 = sw[wip][t + 3];
            float2 f0 = __half22float2(hbase[p0.x]);
            float2 f1 = __half22float2(hbase[p1.x]);
            float2 f2 = __half22float2(hbase[p2.x]);
            float2 f3 = __half22float2(hbase[p3.x]);
            float e0 = __int_as_float(p0.y), e1 = __int_as_float(p1.y);
            float e2 = __int_as_float(p2.y), e3 = __int_as_float(p3.y);
            acc0 = fmaf(e0, f0.x, acc0); acc1 = fmaf(e0, f0.y, acc1);
            acc0 = fmaf(e1, f1.x, acc0); acc1 = fmaf(e1, f1.y, acc1);
            acc0 = fmaf(e2, f2.x, acc0); acc1 = fmaf(e2, f2.y, acc1);
            acc0 = fmaf(e3, f3.x, acc0); acc1 = fmaf(e3, f3.y, acc1);
        }
        for (; t < cnt; ++t) {
            int2 p = sw[wip][t];
            float2 f = __half22float2(hbase[p.x]);
            float ej = __int_as_float(p.y);
            acc0 = fmaf(ej, f.x, acc0);
            acc1 = fmaf(ej, f.y, acc1);
        }
        __syncwarp();
    }
#pragma unroll
    for (int o = 16; o; o >>= 1) den += __shfl_xor_sync(0xffffffffu, den, o);

    float inv = 1.f / den;
    float2 bv = ((const float2*)bias)[lane];
    float o0 = acc0 * inv + bv.x;
    float o1 = acc1 * inv + bv.y;
    o0 = (o0 > 0.f) ? o0 : (__expf(o0) - 1.0f);  // ELU via fast exp
    o1 = (o1 > 0.f) ? o1 : (__expf(o1) - 1.0f);

    // fused layer-2 linear: h2/s2/d2
    float p[DOUT];
#pragma unroll
    for (int c = 0; c < DOUT; ++c)
        p[c] = o0 * W2[(2 * lane) * DOUT + c] + o1 * W2[(2 * lane + 1) * DOUT + c];
#pragma unroll
    for (int c = 0; c < DOUT; ++c)
#pragma unroll
        for (int o = 16; o; o >>= 1) p[c] += __shfl_xor_sync(0xffffffffu, p[c], o);
    if (lane == 0) {
        float s = 0.f, d = 0.f;
#pragma unroll
        for (int c = 0; c < DOUT; ++c) {
            g_h2[(size_t)w * DOUT + c] = p[c];
            s += p[c] * as2[c];
            d += p[c] * ad2[c];
        }
        g_s2[w] = s;
        g_d2[w] = d;
    }
}

// ---------------- layer-2 GAT (C=6, transposed gather: lanes 0-5 own cols) ----------------
__global__ void k_edge6(const float* __restrict__ b2, float* __restrict__ out) {
    __shared__ int2 sw[8][32];
    int tid  = threadIdx.x;
    int wip  = tid >> 5;
    int lane = tid & 31;
    int w    = (blockIdx.x * blockDim.x + tid) >> 5;
    if (w >= NN) return;
    int deg = min(g_cnt[w], MAXDEG);
    const int2* csr = g_csr2d + (size_t)w * MAXDEG;
    float dv = g_d2[w];

    float m_run = -1e30f, den = 0.f, acc = 0.f;   // acc meaningful on lanes 0-5
    for (int base = 0; base < deg; base += 32) {
        int j = base + lane;
        float e = -1e30f;
        int si = 0;
        if (j < deg) {
            si = csr[j].x >> 5;              // unscale
            e = g_s2[si] + dv;
            e = (e > 0.f) ? e : NEG * e;
        }
        float sm = e;
#pragma unroll
        for (int o = 16; o; o >>= 1) sm = fmaxf(sm, __shfl_xor_sync(0xffffffffu, sm, o));
        float newm  = fmaxf(m_run, sm);
        float scale = __expf(m_run - newm);
        den *= scale; acc *= scale;
        m_run = newm;
        float ex = __expf(e - newm);
        den += ex;
        sw[wip][lane] = make_int2(si, __float_as_int(ex));
        __syncwarp();

        int cnt = min(32, deg - base);
        int t = 0;
        for (; t + 4 <= cnt; t += 4) {
            int2 p0 = sw[wip][t + 0];
            int2 p1 = sw[wip][t + 1];
            int2 p2 = sw[wip][t + 2];
            int2 p3 = sw[wip][t + 3];
            float h0 = (lane < DOUT) ? g_h2[p0.x * DOUT + lane] : 0.f;
            float h1 = (lane < DOUT) ? g_h2[p1.x * DOUT + lane] : 0.f;
            float h2v = (lane < DOUT) ? g_h2[p2.x * DOUT + lane] : 0.f;
            float h3 = (lane < DOUT) ? g_h2[p3.x * DOUT + lane] : 0.f;
            acc = fmaf(__int_as_float(p0.y), h0, acc);
            acc = fmaf(__int_as_float(p1.y), h1, acc);
            acc = fmaf(__int_as_float(p2.y), h2v, acc);
            acc = fmaf(__int_as_float(p3.y), h3, acc);
        }
        for (; t < cnt; ++t) {
            int2 p = sw[wip][t];
            float hv = (lane < DOUT) ? g_h2[p.x * DOUT + lane] : 0.f;
            acc = fmaf(__int_as_float(p.y), hv, acc);
        }
        __syncwarp();
    }
#pragma unroll
    for (int o = 16; o; o >>= 1) den += __shfl_xor_sync(0xffffffffu, den, o);

    if (lane < DOUT)
        out[(size_t)w * DOUT + lane] = acc / den + b2[lane];
}

// ---------------- launch ----------------
extern "C" void kernel_launch(void* const* d_in, const int* in_sizes, int n_in,
                              void* d_out, int out_size) {
    const float* x      = (const float*)d_in[0];
    const void*  ei     = d_in[1];
    const float* W1     = (const float*)d_in[2];
    const float* a_src1 = (const float*)d_in[3];
    const float* a_dst1 = (const float*)d_in[4];
    const float* b1     = (const float*)d_in[5];
    const float* W2     = (const float*)d_in[6];
    const float* a_src2 = (const float*)d_in[7];
    const float* a_dst2 = (const float*)d_in[8];
    const float* b2     = (const float*)d_in[9];
    float*       out    = (float*)d_out;

    int E  = in_sizes[1] / 2;
    int EP = E + NN;
    int n_words = in_sizes[1];

    // zero degree counters (graph-capturable async memset)
    void* cnt_ptr = nullptr;
    cudaGetSymbolAddress(&cnt_ptr, g_cnt);
    cudaMemsetAsync(cnt_ptr, 0, NN * sizeof(int));

    // dtype detect (tiny)
    k_detect<<<1, 256>>>((const int*)ei, n_words);

    // layer-1 GEMM (tensor cores) + fused s1/d1  — BEFORE fill so fill can pack s1
    k_gemm1_tc<<<(NN + 127) / 128, 256>>>(x, W1, a_src1, a_dst1);

    // CSR fill: {src*32, s1[src]} pairs
    k_fill2d<<<(EP + 255) / 256, 256>>>(ei, E, EP);

    // layer-1 GAT (online softmax, smem stage) + fused layer-2 linear
    int warp_blocks = (NN * 32 + 255) / 256;
    k_edge64<<<warp_blocks, 256>>>(b1, W2, a_src2, a_dst2);

    // layer-2 GAT (transposed)
    k_edge6<<<warp_blocks, 256>>>(b2, out);
}